// round 14
// baseline (speedup 1.0000x reference)
#include <cuda_runtime.h>
#include <cuda_fp16.h>
#include <cstdint>

// ---------------------------------------------------------------------------
// GCN-VAE encoder. Round 14: round-11 champion (frozen gather arithmetic)
// + degree-bucketed node permutation so each warp processes equal-degree
// nodes (kills intra-warp divergence in the gather). The permutation build
// is folded into the existing scan kernels: zero extra launches.
// ---------------------------------------------------------------------------

#define N_NODES 100000
#define E_MAX   1700000
#define DBINS   64

__device__ int    g_cnt   [N_NODES];
__device__ int    g_off   [N_NODES + 1];
__device__ int    g_cursor[N_NODES];
__device__ int    g_bsum  [128];
__device__ int    g_dhist [DBINS];
__device__ int    g_dcur  [DBINS];
__device__ int    g_perm  [N_NODES];
__device__ int    g_csr   [E_MAX];
__device__ float  g_dinv  [N_NODES];
__device__ __half g_xh  [(size_t)N_NODES * 64];      // fp16 dinv*x
__device__ __half g_aggH[(size_t)N_NODES * 128];     // fp16 aggregated features
__device__ __half g_bufH[(size_t)N_NODES * 128];     // fp16 dinv*hidden
__device__ __half g_wh1 [64  * 128];
__device__ __half g_wh2 [128 * 128];
__device__ __half g_whh [128 * 128];                 // [Wmu | Wlv]

// ----------------------------- setup / CSR ---------------------------------

__global__ void k_setup(int* __restrict__ cnt, int* __restrict__ dhist, int M,
                        const float* __restrict__ W1, const float* __restrict__ W2,
                        const float* __restrict__ Wmu, const float* __restrict__ Wlv,
                        __half* __restrict__ Wh1, __half* __restrict__ Wh2,
                        __half* __restrict__ Whh) {
    int i = blockIdx.x * blockDim.x + threadIdx.x;
    if (i < DBINS) dhist[i] = 0;
    if (i < M) cnt[i] = 0;
    if (i < 64 * 128) Wh1[i] = __float2half_rn(W1[i]);
    if (i < 128 * 128) {
        Wh2[i] = __float2half_rn(W2[i]);
        int k = i >> 7, j = i & 127;
        Whh[i] = __float2half_rn(j < 64 ? Wmu[k * 64 + j] : Wlv[k * 64 + (j - 64)]);
    }
}

__global__ void k_hist(const int* __restrict__ dst, int* __restrict__ cnt, int E) {
    int i = blockIdx.x * blockDim.x + threadIdx.x;
    if (i < E) atomicAdd(&cnt[dst[i]], 1);
}

// scan1: block-local exclusive scan of cnt + 64-bin degree histogram
__global__ void k_scan1(const int* __restrict__ cnt, int* __restrict__ off,
                        int* __restrict__ bsum, int* __restrict__ dhist, int n) {
    __shared__ int s[256];
    __shared__ int dh[DBINS];
    const int tid = threadIdx.x;
    const int base = blockIdx.x * 1024 + tid * 4;
    if (tid < DBINS) dh[tid] = 0;
    int v[4], tsum = 0;
#pragma unroll
    for (int r = 0; r < 4; r++) {
        int idx = base + r;
        v[r] = (idx < n) ? cnt[idx] : 0;
        tsum += v[r];
    }
    s[tid] = tsum;
    __syncthreads();
#pragma unroll
    for (int r = 0; r < 4; r++) {
        int idx = base + r;
        if (idx < n) atomicAdd(&dh[v[r] < DBINS ? v[r] : DBINS - 1], 1);
    }
    for (int d = 1; d < 256; d <<= 1) {
        int add = (tid >= d) ? s[tid - d] : 0;
        __syncthreads();
        s[tid] += add;
        __syncthreads();
    }
    int run = s[tid] - tsum;
#pragma unroll
    for (int r = 0; r < 4; r++) {
        int idx = base + r;
        if (idx < n) off[idx] = run;
        run += v[r];
    }
    if (tid == 255) bsum[blockIdx.x] = s[255];
    __syncthreads();
    if (tid < DBINS && dh[tid] > 0) atomicAdd(&dhist[tid], dh[tid]);
}

// scan2: exclusive scan of bsum (<=128) AND of the 64-bin degree histogram
__global__ void k_scan2(int* __restrict__ bsum, int nb,
                        const int* __restrict__ dhist, int* __restrict__ dcur) {
    __shared__ int s[128];
    int tid = threadIdx.x;
    int v = (tid < nb) ? bsum[tid] : 0;
    s[tid] = v;
    __syncthreads();
    for (int d = 1; d < 128; d <<= 1) {
        int add = (tid >= d) ? s[tid - d] : 0;
        __syncthreads();
        s[tid] += add;
        __syncthreads();
    }
    if (tid < nb) bsum[tid] = s[tid] - v;
    __syncthreads();
    // degree-bin scan
    int dv = (tid < DBINS) ? dhist[tid] : 0;
    s[tid] = dv;
    __syncthreads();
    for (int d = 1; d < DBINS; d <<= 1) {
        int add = (tid >= d && tid < DBINS) ? s[tid - d] : 0;
        __syncthreads();
        if (tid < DBINS) s[tid] += add;
        __syncthreads();
    }
    if (tid < DBINS) dcur[tid] = s[tid] - dv;
}

// scan3: finalize off/cursor/dinv AND scatter node ids into degree-sorted perm
__global__ void k_scan3(int* __restrict__ off, int* __restrict__ cursor,
                        const int* __restrict__ bsum, const int* __restrict__ cnt,
                        float* __restrict__ dinv, int* __restrict__ dcur,
                        int* __restrict__ perm, int n, int E) {
    int i = blockIdx.x * blockDim.x + threadIdx.x;
    if (i < n) {
        int o = off[i] + bsum[i >> 10];
        off[i] = o;
        cursor[i] = o;
        int deg = cnt[i];
        dinv[i] = rsqrtf((float)(deg + 1));
        int bin = deg < DBINS ? deg : DBINS - 1;
        int pos = atomicAdd(&dcur[bin], 1);
        perm[pos] = i;
    }
    if (i == 0) off[n] = E;
}

__global__ void k_fill(const int* __restrict__ src, const int* __restrict__ dst,
                       int* __restrict__ cursor, int* __restrict__ csr, int E) {
    int i = blockIdx.x * blockDim.x + threadIdx.x;
    if (i < E) {
        int pos = atomicAdd(&cursor[dst[i]], 1);
        csr[pos] = src[i];
    }
}

// ----------------------- x -> fp16(dinv * x) --------------------------------

__global__ void k_cvt(const float* __restrict__ in, const float* __restrict__ dinv,
                      __half* __restrict__ outp, int M) {
    int i = blockIdx.x * blockDim.x + threadIdx.x;   // one uint4 (8 halves)
    if (i >= M * 8) return;
    int row = i >> 3;
    float w = dinv[row];
    float4 a = reinterpret_cast<const float4*>(in)[2 * i];
    float4 b = reinterpret_cast<const float4*>(in)[2 * i + 1];
    __half2 h[4];
    h[0] = __float22half2_rn(make_float2(w * a.x, w * a.y));
    h[1] = __float22half2_rn(make_float2(w * a.z, w * a.w));
    h[2] = __float22half2_rn(make_float2(w * b.x, w * b.y));
    h[3] = __float22half2_rn(make_float2(w * b.z, w * b.w));
    reinterpret_cast<uint4*>(outp)[i] = *reinterpret_cast<uint4*>(h);
}

// ----------------------------- gather SpMM ----------------------------------
// agg = fp16( dinv_i * ( t'[i] + sum_j t'[j] ) ),  t' = dinv*t.
// G = D/8 lanes per node; lane owns one uint4 (8 halves).
// Node order comes from the degree-sorted perm: all nodes in a warp have
// (near-)equal degree -> no intra-warp loop divergence.
// Loop arithmetic identical to round-11 champion (depth-1 HADD2 pairs).

template <int D>
__global__ void __launch_bounds__(256)
k_gather_h(__half* __restrict__ acc, const __half* __restrict__ t,
           const int* __restrict__ csr, const int* __restrict__ off,
           const float* __restrict__ dinv, const int* __restrict__ perm, int n) {
    constexpr int G = D / 8;
    int g    = (blockIdx.x * blockDim.x + threadIdx.x) / G;
    int lane = threadIdx.x % G;
    if (g >= n) return;
    int gid = perm[g];

    float a[8];
    {
        uint4 u = *reinterpret_cast<const uint4*>(t + (size_t)gid * D + lane * 8);
        const __half2* h = reinterpret_cast<const __half2*>(&u);
#pragma unroll
        for (int p = 0; p < 4; p++) {
            float2 f = __half22float2(h[p]);
            a[2 * p]     = f.x;
            a[2 * p + 1] = f.y;
        }
    }

    int e   = off[gid];
    int end = off[gid + 1];
    for (; e + 4 <= end; e += 4) {
        int s0 = csr[e], s1 = csr[e + 1], s2 = csr[e + 2], s3 = csr[e + 3];
        uint4 u0 = *reinterpret_cast<const uint4*>(t + (size_t)s0 * D + lane * 8);
        uint4 u1 = *reinterpret_cast<const uint4*>(t + (size_t)s1 * D + lane * 8);
        uint4 u2 = *reinterpret_cast<const uint4*>(t + (size_t)s2 * D + lane * 8);
        uint4 u3 = *reinterpret_cast<const uint4*>(t + (size_t)s3 * D + lane * 8);
        const __half2* h0 = reinterpret_cast<const __half2*>(&u0);
        const __half2* h1 = reinterpret_cast<const __half2*>(&u1);
        const __half2* h2 = reinterpret_cast<const __half2*>(&u2);
        const __half2* h3 = reinterpret_cast<const __half2*>(&u3);
#pragma unroll
        for (int p = 0; p < 4; p++) {
            __half2 s01 = __hadd2(h0[p], h1[p]);   // fp16 pairwise pre-add
            __half2 s23 = __hadd2(h2[p], h3[p]);
            float2 f01 = __half22float2(s01);
            float2 f23 = __half22float2(s23);
            a[2 * p]     += f01.x + f23.x;
            a[2 * p + 1] += f01.y + f23.y;
        }
    }
    if (e + 2 <= end) {
        int s0 = csr[e], s1 = csr[e + 1];
        e += 2;
        uint4 u0 = *reinterpret_cast<const uint4*>(t + (size_t)s0 * D + lane * 8);
        uint4 u1 = *reinterpret_cast<const uint4*>(t + (size_t)s1 * D + lane * 8);
        const __half2* h0 = reinterpret_cast<const __half2*>(&u0);
        const __half2* h1 = reinterpret_cast<const __half2*>(&u1);
#pragma unroll
        for (int p = 0; p < 4; p++) {
            __half2 s01 = __hadd2(h0[p], h1[p]);
            float2 f01 = __half22float2(s01);
            a[2 * p]     += f01.x;
            a[2 * p + 1] += f01.y;
        }
    }
    if (e < end) {
        int s0 = csr[e];
        uint4 u0 = *reinterpret_cast<const uint4*>(t + (size_t)s0 * D + lane * 8);
        const __half2* h0 = reinterpret_cast<const __half2*>(&u0);
#pragma unroll
        for (int p = 0; p < 4; p++) {
            float2 f0 = __half22float2(h0[p]);
            a[2 * p]     += f0.x;
            a[2 * p + 1] += f0.y;
        }
    }

    float w = dinv[gid];
    __half2 hv[4];
#pragma unroll
    for (int p = 0; p < 4; p++)
        hv[p] = __float22half2_rn(make_float2(w * a[2 * p], w * a[2 * p + 1]));
    *reinterpret_cast<uint4*>(acc + (size_t)gid * D + lane * 8) =
        *reinterpret_cast<uint4*>(hv);
}

// ------------------------------- HMMA GEMM ----------------------------------

template <int K, bool RELU, bool SPLIT>
__global__ void __launch_bounds__(256)
k_hgemm(const __half* __restrict__ A, const __half* __restrict__ Wh,
        const float* __restrict__ b0, const float* __restrict__ b1,
        const float* __restrict__ dinv,
        __half* __restrict__ H, float* __restrict__ C0, float* __restrict__ C1,
        int M) {
    __shared__ __half Xs[128][72];
    __shared__ __half Ws[64][136];

    const int tid = threadIdx.x;
    const int wid = tid >> 5;
    const int lane = tid & 31;
    const int mg = wid >> 1;
    const int ng = wid & 1;
    const int row0 = blockIdx.x * 128;

    float acc[2][8][4];
#pragma unroll
    for (int mt = 0; mt < 2; mt++)
#pragma unroll
        for (int nt = 0; nt < 8; nt++)
#pragma unroll
            for (int q = 0; q < 4; q++) acc[mt][nt][q] = 0.f;

    for (int kc = 0; kc < K; kc += 64) {
#pragma unroll
        for (int i = tid; i < 128 * 8; i += 256) {
            int r = i >> 3, c8 = i & 7;
            int grow = row0 + r;
            uint4 v = make_uint4(0u, 0u, 0u, 0u);
            if (grow < M)
                v = *reinterpret_cast<const uint4*>(A + (size_t)grow * K + kc + c8 * 8);
            *reinterpret_cast<uint4*>(&Xs[r][c8 * 8]) = v;
        }
#pragma unroll
        for (int i = tid; i < 64 * 16; i += 256) {
            int k = i >> 4, n8 = i & 15;
            uint4 v = *reinterpret_cast<const uint4*>(Wh + (size_t)(kc + k) * 128 + n8 * 8);
            *reinterpret_cast<uint4*>(&Ws[k][n8 * 8]) = v;
        }
        __syncthreads();

#pragma unroll
        for (int ks = 0; ks < 4; ks++) {
            uint32_t af[2][4];
#pragma unroll
            for (int mt = 0; mt < 2; mt++) {
                int r = mg * 32 + mt * 16 + (lane & 15);
                int c = ks * 16 + (lane >> 4) * 8;
                uint32_t addr = (uint32_t)__cvta_generic_to_shared(&Xs[r][c]);
                asm volatile(
                    "ldmatrix.sync.aligned.m8n8.x4.shared.b16 {%0,%1,%2,%3}, [%4];"
                    : "=r"(af[mt][0]), "=r"(af[mt][1]), "=r"(af[mt][2]), "=r"(af[mt][3])
                    : "r"(addr));
            }
#pragma unroll
            for (int nt = 0; nt < 8; nt++) {
                int k = ks * 16 + (lane & 15);
                int c = ng * 64 + nt * 8;
                uint32_t addr = (uint32_t)__cvta_generic_to_shared(&Ws[k][c]);
                uint32_t bf0, bf1;
                asm volatile(
                    "ldmatrix.sync.aligned.m8n8.x2.trans.shared.b16 {%0,%1}, [%2];"
                    : "=r"(bf0), "=r"(bf1) : "r"(addr));
#pragma unroll
                for (int mt = 0; mt < 2; mt++) {
                    asm volatile(
                        "mma.sync.aligned.m16n8k16.row.col.f32.f16.f16.f32 "
                        "{%0,%1,%2,%3}, {%4,%5,%6,%7}, {%8,%9}, {%0,%1,%2,%3};"
                        : "+f"(acc[mt][nt][0]), "+f"(acc[mt][nt][1]),
                          "+f"(acc[mt][nt][2]), "+f"(acc[mt][nt][3])
                        : "r"(af[mt][0]), "r"(af[mt][1]), "r"(af[mt][2]), "r"(af[mt][3]),
                          "r"(bf0), "r"(bf1));
                }
            }
        }
        __syncthreads();
    }

    const int tig = lane & 3;
    const int grp = lane >> 2;
#pragma unroll
    for (int mt = 0; mt < 2; mt++) {
#pragma unroll
        for (int nt = 0; nt < 8; nt++) {
            int c = ng * 64 + nt * 8 + tig * 2;
#pragma unroll
            for (int hf = 0; hf < 2; hf++) {
                int r = row0 + mg * 32 + mt * 16 + grp + hf * 8;
                if (r >= M) continue;
                float v0 = acc[mt][nt][hf * 2 + 0];
                float v1 = acc[mt][nt][hf * 2 + 1];
                if (!SPLIT) {
                    v0 += b0[c]; v1 += b0[c + 1];
                    if (RELU) { v0 = fmaxf(v0, 0.f); v1 = fmaxf(v1, 0.f); }
                    float dv = dinv[r];
                    *reinterpret_cast<__half2*>(H + (size_t)r * 128 + c) =
                        __floats2half2_rn(v0 * dv, v1 * dv);
                } else if (c < 64) {
                    v0 += b0[c]; v1 += b0[c + 1];
                    *reinterpret_cast<float2*>(C0 + (size_t)r * 64 + c) =
                        make_float2(v0, v1);
                } else {
                    v0 += b1[c - 64]; v1 += b1[c - 63];
                    *reinterpret_cast<float2*>(C1 + (size_t)r * 64 + (c - 64)) =
                        make_float2(v0, v1);
                }
            }
        }
    }
}

// ------------------------------- launcher ----------------------------------

extern "C" void kernel_launch(void* const* d_in, const int* in_sizes, int n_in,
                              void* d_out, int out_size) {
    const float* x   = (const float*)d_in[0];
    const int*   ei  = (const int*)  d_in[1];
    const float* W1  = (const float*)d_in[2];
    const float* b1  = (const float*)d_in[3];
    const float* W2  = (const float*)d_in[4];
    const float* b2  = (const float*)d_in[5];
    const float* Wmu = (const float*)d_in[6];
    const float* bmu = (const float*)d_in[7];
    const float* Wlv = (const float*)d_in[8];
    const float* blv = (const float*)d_in[9];
    float* out = (float*)d_out;

    const int M = in_sizes[0] / 64;
    const int E = in_sizes[1] / 2;
    const int* src = ei;
    const int* dst = ei + E;

    int *cnt, *off, *cursor, *bsum, *csr, *dhist, *dcur, *perm;
    float *dinv;
    __half *xh, *aggH, *bufH, *wh1, *wh2, *whh;
    cudaGetSymbolAddress((void**)&cnt,    g_cnt);
    cudaGetSymbolAddress((void**)&off,    g_off);
    cudaGetSymbolAddress((void**)&cursor, g_cursor);
    cudaGetSymbolAddress((void**)&bsum,   g_bsum);
    cudaGetSymbolAddress((void**)&csr,    g_csr);
    cudaGetSymbolAddress((void**)&dhist,  g_dhist);
    cudaGetSymbolAddress((void**)&dcur,   g_dcur);
    cudaGetSymbolAddress((void**)&perm,   g_perm);
    cudaGetSymbolAddress((void**)&dinv,   g_dinv);
    cudaGetSymbolAddress((void**)&xh,     g_xh);
    cudaGetSymbolAddress((void**)&aggH,   g_aggH);
    cudaGetSymbolAddress((void**)&bufH,   g_bufH);
    cudaGetSymbolAddress((void**)&wh1,    g_wh1);
    cudaGetSymbolAddress((void**)&wh2,    g_wh2);
    cudaGetSymbolAddress((void**)&whh,    g_whh);

    const int T = 256;
    auto nb = [](long n, int t) { return (int)((n + t - 1) / t); };
    const int nscan = nb(M, 1024);
    const int gB = nb(M, 128);

    // setup + CSR build (by dst) + dinv + degree-sorted perm + x prescale
    k_setup<<<nb(M, T), T>>>(cnt, dhist, M, W1, W2, Wmu, Wlv, wh1, wh2, whh);
    k_hist <<<nb(E, T), T>>>(dst, cnt, E);
    k_scan1<<<nscan, 256>>>(cnt, off, bsum, dhist, M);
    k_scan2<<<1, 128>>>(bsum, nscan, dhist, dcur);
    k_scan3<<<nb(M, T), T>>>(off, cursor, bsum, cnt, dinv, dcur, perm, M, E);
    k_fill <<<nb(E, T), T>>>(src, dst, cursor, csr, E);
    k_cvt  <<<nb((long)M * 8, T), T>>>(x, dinv, xh, M);

    // layer 1: gather xh (64) -> HMMA 64->128 relu -> h1' fp16 (prescaled)
    k_gather_h<64><<<nb((long)M * 8, T), T>>>(aggH, xh, csr, off, dinv, perm, M);
    k_hgemm<64, true, false><<<gB, 256>>>(aggH, wh1, b1, nullptr, dinv,
                                          bufH, nullptr, nullptr, M);

    // layer 2: gather h1' (128) -> HMMA 128->128 relu -> h2' fp16 (prescaled)
    k_gather_h<128><<<nb((long)M * 16, T), T>>>(aggH, bufH, csr, off, dinv, perm, M);
    k_hgemm<128, true, false><<<gB, 256>>>(aggH, wh2, b2, nullptr, dinv,
                                           bufH, nullptr, nullptr, M);

    // heads: gather h2' (128) once -> fused mu|logvar HMMA (fp32 split out)
    k_gather_h<128><<<nb((long)M * 16, T), T>>>(aggH, bufH, csr, off, dinv, perm, M);
    k_hgemm<128, false, true><<<gB, 256>>>(aggH, whh, bmu, blv, dinv,
                                           nullptr, out, out + (size_t)M * 64, M);
}

// round 15
// speedup vs baseline: 1.0893x; 1.0893x over previous
#include <cuda_runtime.h>
#include <cuda_fp16.h>
#include <cstdint>

// ---------------------------------------------------------------------------
// GCN-VAE encoder. Round 15: round-11 champion with FROZEN gather/GEMM,
// launch-count reduction only:
//   - k_scan2 folded into k_scan3 (per-block bsum prefix, proven in R12 prof)
//   - k_cvt folded into the same kernel (computes rsqrtf(cnt+1) inline)
//   13 -> 11 kernel launches. All hot kernels byte-identical to round 11.
// ---------------------------------------------------------------------------

#define N_NODES 100000
#define E_MAX   1700000

__device__ int    g_cnt   [N_NODES];
__device__ int    g_off   [N_NODES + 1];
__device__ int    g_cursor[N_NODES];
__device__ int    g_bsum  [128];
__device__ int    g_csr   [E_MAX];
__device__ float  g_dinv  [N_NODES];
__device__ __half g_xh  [(size_t)N_NODES * 64];      // fp16 dinv*x
__device__ __half g_aggH[(size_t)N_NODES * 128];     // fp16 aggregated features
__device__ __half g_bufH[(size_t)N_NODES * 128];     // fp16 dinv*hidden
__device__ __half g_wh1 [64  * 128];
__device__ __half g_wh2 [128 * 128];
__device__ __half g_whh [128 * 128];                 // [Wmu | Wlv]

// ----------------------------- setup / CSR ---------------------------------

__global__ void k_setup(int* __restrict__ cnt, int M,
                        const float* __restrict__ W1, const float* __restrict__ W2,
                        const float* __restrict__ Wmu, const float* __restrict__ Wlv,
                        __half* __restrict__ Wh1, __half* __restrict__ Wh2,
                        __half* __restrict__ Whh) {
    int i = blockIdx.x * blockDim.x + threadIdx.x;
    if (i < M) cnt[i] = 0;
    if (i < 64 * 128) Wh1[i] = __float2half_rn(W1[i]);
    if (i < 128 * 128) {
        Wh2[i] = __float2half_rn(W2[i]);
        int k = i >> 7, j = i & 127;
        Whh[i] = __float2half_rn(j < 64 ? Wmu[k * 64 + j] : Wlv[k * 64 + (j - 64)]);
    }
}

__global__ void k_hist(const int* __restrict__ dst, int* __restrict__ cnt, int E) {
    int i = blockIdx.x * blockDim.x + threadIdx.x;
    if (i < E) atomicAdd(&cnt[dst[i]], 1);
}

__global__ void k_scan1(const int* __restrict__ cnt, int* __restrict__ off,
                        int* __restrict__ bsum, int n) {
    __shared__ int s[256];
    const int tid = threadIdx.x;
    const int base = blockIdx.x * 1024 + tid * 4;
    int v[4], tsum = 0;
#pragma unroll
    for (int r = 0; r < 4; r++) {
        int idx = base + r;
        v[r] = (idx < n) ? cnt[idx] : 0;
        tsum += v[r];
    }
    s[tid] = tsum;
    __syncthreads();
    for (int d = 1; d < 256; d <<= 1) {
        int add = (tid >= d) ? s[tid - d] : 0;
        __syncthreads();
        s[tid] += add;
        __syncthreads();
    }
    int run = s[tid] - tsum;
#pragma unroll
    for (int r = 0; r < 4; r++) {
        int idx = base + r;
        if (idx < n) off[idx] = run;
        run += v[r];
    }
    if (tid == 255) bsum[blockIdx.x] = s[255];
}

// Fused: (a) per-block bsum prefix (replaces k_scan2), finalize off/cursor/dinv
//        (b) x -> fp16(rsqrt(cnt+1) * x) conversion (replaces k_cvt)
// Grid covers M*8 threads (one uint4 of x per thread); first M do scan work.
__global__ void __launch_bounds__(256)
k_scan3_cvt(int* __restrict__ off, int* __restrict__ cursor,
            const int* __restrict__ bsum, const int* __restrict__ cnt,
            float* __restrict__ dinv, int n, int E, int nscan,
            const float* __restrict__ x, __half* __restrict__ xh) {
    __shared__ int s[128];
    __shared__ int pre;
    const int tid = threadIdx.x;
    const long base = (long)blockIdx.x * 256;

    // scan-finalize part (only blocks overlapping [0, n))
    if (base < n) {
        const int blk = (int)(base >> 10);   // constant within a 256-block
        if (tid < 128) s[tid] = (tid < blk && tid < nscan) ? bsum[tid] : 0;
        __syncthreads();
        if (tid < 64) s[tid] += s[tid + 64];
        __syncthreads();
        if (tid < 32) {
            int v = s[tid] + s[tid + 32];
#pragma unroll
            for (int o = 16; o > 0; o >>= 1)
                v += __shfl_down_sync(0xffffffffu, v, o);
            if (tid == 0) pre = v;
        }
        __syncthreads();

        int i = (int)base + tid;
        if (i < n) {
            int o = off[i] + pre;
            off[i] = o;
            cursor[i] = o;
            dinv[i] = rsqrtf((float)(cnt[i] + 1));
        }
        if (i == 0) off[n] = E;
    }

    // cvt part: one uint4 (8 halves of x) per thread, w from cnt directly
    long j = base + tid;
    if (j < (long)n * 8) {
        int row = (int)(j >> 3);
        float w = rsqrtf((float)(cnt[row] + 1));
        float4 a = reinterpret_cast<const float4*>(x)[2 * j];
        float4 b = reinterpret_cast<const float4*>(x)[2 * j + 1];
        __half2 h[4];
        h[0] = __float22half2_rn(make_float2(w * a.x, w * a.y));
        h[1] = __float22half2_rn(make_float2(w * a.z, w * a.w));
        h[2] = __float22half2_rn(make_float2(w * b.x, w * b.y));
        h[3] = __float22half2_rn(make_float2(w * b.z, w * b.w));
        reinterpret_cast<uint4*>(xh)[j] = *reinterpret_cast<uint4*>(h);
    }
}

__global__ void k_fill(const int* __restrict__ src, const int* __restrict__ dst,
                       int* __restrict__ cursor, int* __restrict__ csr, int E) {
    int i = blockIdx.x * blockDim.x + threadIdx.x;
    if (i < E) {
        int pos = atomicAdd(&cursor[dst[i]], 1);
        csr[pos] = src[i];
    }
}

// ----------------------------- gather SpMM ----------------------------------
// agg = fp16( dinv_i * ( t'[i] + sum_j t'[j] ) ),  t' = dinv*t.
// G = D/8 lanes per node; lane owns one uint4 (8 halves).
// FROZEN round-11 design: 4-edge loop, depth-1 HADD2 pairs.

template <int D>
__global__ void __launch_bounds__(256)
k_gather_h(__half* __restrict__ acc, const __half* __restrict__ t,
           const int* __restrict__ csr, const int* __restrict__ off,
           const float* __restrict__ dinv, int n) {
    constexpr int G = D / 8;
    int gid  = (blockIdx.x * blockDim.x + threadIdx.x) / G;
    int lane = threadIdx.x % G;
    if (gid >= n) return;

    float a[8];
    {
        uint4 u = *reinterpret_cast<const uint4*>(t + (size_t)gid * D + lane * 8);
        const __half2* h = reinterpret_cast<const __half2*>(&u);
#pragma unroll
        for (int p = 0; p < 4; p++) {
            float2 f = __half22float2(h[p]);
            a[2 * p]     = f.x;
            a[2 * p + 1] = f.y;
        }
    }

    int e   = off[gid];
    int end = off[gid + 1];
    for (; e + 4 <= end; e += 4) {
        int s0 = csr[e], s1 = csr[e + 1], s2 = csr[e + 2], s3 = csr[e + 3];
        uint4 u0 = *reinterpret_cast<const uint4*>(t + (size_t)s0 * D + lane * 8);
        uint4 u1 = *reinterpret_cast<const uint4*>(t + (size_t)s1 * D + lane * 8);
        uint4 u2 = *reinterpret_cast<const uint4*>(t + (size_t)s2 * D + lane * 8);
        uint4 u3 = *reinterpret_cast<const uint4*>(t + (size_t)s3 * D + lane * 8);
        const __half2* h0 = reinterpret_cast<const __half2*>(&u0);
        const __half2* h1 = reinterpret_cast<const __half2*>(&u1);
        const __half2* h2 = reinterpret_cast<const __half2*>(&u2);
        const __half2* h3 = reinterpret_cast<const __half2*>(&u3);
#pragma unroll
        for (int p = 0; p < 4; p++) {
            __half2 s01 = __hadd2(h0[p], h1[p]);   // fp16 pairwise pre-add
            __half2 s23 = __hadd2(h2[p], h3[p]);
            float2 f01 = __half22float2(s01);
            float2 f23 = __half22float2(s23);
            a[2 * p]     += f01.x + f23.x;
            a[2 * p + 1] += f01.y + f23.y;
        }
    }
    if (e + 2 <= end) {
        int s0 = csr[e], s1 = csr[e + 1];
        e += 2;
        uint4 u0 = *reinterpret_cast<const uint4*>(t + (size_t)s0 * D + lane * 8);
        uint4 u1 = *reinterpret_cast<const uint4*>(t + (size_t)s1 * D + lane * 8);
        const __half2* h0 = reinterpret_cast<const __half2*>(&u0);
        const __half2* h1 = reinterpret_cast<const __half2*>(&u1);
#pragma unroll
        for (int p = 0; p < 4; p++) {
            __half2 s01 = __hadd2(h0[p], h1[p]);
            float2 f01 = __half22float2(s01);
            a[2 * p]     += f01.x;
            a[2 * p + 1] += f01.y;
        }
    }
    if (e < end) {
        int s0 = csr[e];
        uint4 u0 = *reinterpret_cast<const uint4*>(t + (size_t)s0 * D + lane * 8);
        const __half2* h0 = reinterpret_cast<const __half2*>(&u0);
#pragma unroll
        for (int p = 0; p < 4; p++) {
            float2 f0 = __half22float2(h0[p]);
            a[2 * p]     += f0.x;
            a[2 * p + 1] += f0.y;
        }
    }

    float w = dinv[gid];
    __half2 hv[4];
#pragma unroll
    for (int p = 0; p < 4; p++)
        hv[p] = __float22half2_rn(make_float2(w * a[2 * p], w * a[2 * p + 1]));
    *reinterpret_cast<uint4*>(acc + (size_t)gid * D + lane * 8) =
        *reinterpret_cast<uint4*>(hv);
}

// ------------------------------- HMMA GEMM ----------------------------------

template <int K, bool RELU, bool SPLIT>
__global__ void __launch_bounds__(256)
k_hgemm(const __half* __restrict__ A, const __half* __restrict__ Wh,
        const float* __restrict__ b0, const float* __restrict__ b1,
        const float* __restrict__ dinv,
        __half* __restrict__ H, float* __restrict__ C0, float* __restrict__ C1,
        int M) {
    __shared__ __half Xs[128][72];
    __shared__ __half Ws[64][136];

    const int tid = threadIdx.x;
    const int wid = tid >> 5;
    const int lane = tid & 31;
    const int mg = wid >> 1;
    const int ng = wid & 1;
    const int row0 = blockIdx.x * 128;

    float acc[2][8][4];
#pragma unroll
    for (int mt = 0; mt < 2; mt++)
#pragma unroll
        for (int nt = 0; nt < 8; nt++)
#pragma unroll
            for (int q = 0; q < 4; q++) acc[mt][nt][q] = 0.f;

    for (int kc = 0; kc < K; kc += 64) {
#pragma unroll
        for (int i = tid; i < 128 * 8; i += 256) {
            int r = i >> 3, c8 = i & 7;
            int grow = row0 + r;
            uint4 v = make_uint4(0u, 0u, 0u, 0u);
            if (grow < M)
                v = *reinterpret_cast<const uint4*>(A + (size_t)grow * K + kc + c8 * 8);
            *reinterpret_cast<uint4*>(&Xs[r][c8 * 8]) = v;
        }
#pragma unroll
        for (int i = tid; i < 64 * 16; i += 256) {
            int k = i >> 4, n8 = i & 15;
            uint4 v = *reinterpret_cast<const uint4*>(Wh + (size_t)(kc + k) * 128 + n8 * 8);
            *reinterpret_cast<uint4*>(&Ws[k][n8 * 8]) = v;
        }
        __syncthreads();

#pragma unroll
        for (int ks = 0; ks < 4; ks++) {
            uint32_t af[2][4];
#pragma unroll
            for (int mt = 0; mt < 2; mt++) {
                int r = mg * 32 + mt * 16 + (lane & 15);
                int c = ks * 16 + (lane >> 4) * 8;
                uint32_t addr = (uint32_t)__cvta_generic_to_shared(&Xs[r][c]);
                asm volatile(
                    "ldmatrix.sync.aligned.m8n8.x4.shared.b16 {%0,%1,%2,%3}, [%4];"
                    : "=r"(af[mt][0]), "=r"(af[mt][1]), "=r"(af[mt][2]), "=r"(af[mt][3])
                    : "r"(addr));
            }
#pragma unroll
            for (int nt = 0; nt < 8; nt++) {
                int k = ks * 16 + (lane & 15);
                int c = ng * 64 + nt * 8;
                uint32_t addr = (uint32_t)__cvta_generic_to_shared(&Ws[k][c]);
                uint32_t bf0, bf1;
                asm volatile(
                    "ldmatrix.sync.aligned.m8n8.x2.trans.shared.b16 {%0,%1}, [%2];"
                    : "=r"(bf0), "=r"(bf1) : "r"(addr));
#pragma unroll
                for (int mt = 0; mt < 2; mt++) {
                    asm volatile(
                        "mma.sync.aligned.m16n8k16.row.col.f32.f16.f16.f32 "
                        "{%0,%1,%2,%3}, {%4,%5,%6,%7}, {%8,%9}, {%0,%1,%2,%3};"
                        : "+f"(acc[mt][nt][0]), "+f"(acc[mt][nt][1]),
                          "+f"(acc[mt][nt][2]), "+f"(acc[mt][nt][3])
                        : "r"(af[mt][0]), "r"(af[mt][1]), "r"(af[mt][2]), "r"(af[mt][3]),
                          "r"(bf0), "r"(bf1));
                }
            }
        }
        __syncthreads();
    }

    const int tig = lane & 3;
    const int grp = lane >> 2;
#pragma unroll
    for (int mt = 0; mt < 2; mt++) {
#pragma unroll
        for (int nt = 0; nt < 8; nt++) {
            int c = ng * 64 + nt * 8 + tig * 2;
#pragma unroll
            for (int hf = 0; hf < 2; hf++) {
                int r = row0 + mg * 32 + mt * 16 + grp + hf * 8;
                if (r >= M) continue;
                float v0 = acc[mt][nt][hf * 2 + 0];
                float v1 = acc[mt][nt][hf * 2 + 1];
                if (!SPLIT) {
                    v0 += b0[c]; v1 += b0[c + 1];
                    if (RELU) { v0 = fmaxf(v0, 0.f); v1 = fmaxf(v1, 0.f); }
                    float dv = dinv[r];
                    *reinterpret_cast<__half2*>(H + (size_t)r * 128 + c) =
                        __floats2half2_rn(v0 * dv, v1 * dv);
                } else if (c < 64) {
                    v0 += b0[c]; v1 += b0[c + 1];
                    *reinterpret_cast<float2*>(C0 + (size_t)r * 64 + c) =
                        make_float2(v0, v1);
                } else {
                    v0 += b1[c - 64]; v1 += b1[c - 63];
                    *reinterpret_cast<float2*>(C1 + (size_t)r * 64 + (c - 64)) =
                        make_float2(v0, v1);
                }
            }
        }
    }
}

// ------------------------------- launcher ----------------------------------

extern "C" void kernel_launch(void* const* d_in, const int* in_sizes, int n_in,
                              void* d_out, int out_size) {
    const float* x   = (const float*)d_in[0];
    const int*   ei  = (const int*)  d_in[1];
    const float* W1  = (const float*)d_in[2];
    const float* b1  = (const float*)d_in[3];
    const float* W2  = (const float*)d_in[4];
    const float* b2  = (const float*)d_in[5];
    const float* Wmu = (const float*)d_in[6];
    const float* bmu = (const float*)d_in[7];
    const float* Wlv = (const float*)d_in[8];
    const float* blv = (const float*)d_in[9];
    float* out = (float*)d_out;

    const int M = in_sizes[0] / 64;
    const int E = in_sizes[1] / 2;
    const int* src = ei;
    const int* dst = ei + E;

    int *cnt, *off, *cursor, *bsum, *csr;
    float *dinv;
    __half *xh, *aggH, *bufH, *wh1, *wh2, *whh;
    cudaGetSymbolAddress((void**)&cnt,    g_cnt);
    cudaGetSymbolAddress((void**)&off,    g_off);
    cudaGetSymbolAddress((void**)&cursor, g_cursor);
    cudaGetSymbolAddress((void**)&bsum,   g_bsum);
    cudaGetSymbolAddress((void**)&csr,    g_csr);
    cudaGetSymbolAddress((void**)&dinv,   g_dinv);
    cudaGetSymbolAddress((void**)&xh,     g_xh);
    cudaGetSymbolAddress((void**)&aggH,   g_aggH);
    cudaGetSymbolAddress((void**)&bufH,   g_bufH);
    cudaGetSymbolAddress((void**)&wh1,    g_wh1);
    cudaGetSymbolAddress((void**)&wh2,    g_wh2);
    cudaGetSymbolAddress((void**)&whh,    g_whh);

    const int T = 256;
    auto nb = [](long n, int t) { return (int)((n + t - 1) / t); };
    const int nscan = nb(M, 1024);
    const int gB = nb(M, 128);

    // setup + CSR build (by dst) + fused scan-finalize/dinv/x-prescale
    k_setup<<<nb(M, T), T>>>(cnt, M, W1, W2, Wmu, Wlv, wh1, wh2, whh);
    k_hist <<<nb(E, T), T>>>(dst, cnt, E);
    k_scan1<<<nscan, 256>>>(cnt, off, bsum, M);
    k_scan3_cvt<<<nb((long)M * 8, T), T>>>(off, cursor, bsum, cnt, dinv,
                                           M, E, nscan, x, xh);
    k_fill <<<nb(E, T), T>>>(src, dst, cursor, csr, E);

    // layer 1: gather xh (64) -> HMMA 64->128 relu -> h1' fp16 (prescaled)
    k_gather_h<64><<<nb((long)M * 8, T), T>>>(aggH, xh, csr, off, dinv, M);
    k_hgemm<64, true, false><<<gB, 256>>>(aggH, wh1, b1, nullptr, dinv,
                                          bufH, nullptr, nullptr, M);

    // layer 2: gather h1' (128) -> HMMA 128->128 relu -> h2' fp16 (prescaled)
    k_gather_h<128><<<nb((long)M * 16, T), T>>>(aggH, bufH, csr, off, dinv, M);
    k_hgemm<128, true, false><<<gB, 256>>>(aggH, wh2, b2, nullptr, dinv,
                                           bufH, nullptr, nullptr, M);

    // heads: gather h2' (128) once -> fused mu|logvar HMMA (fp32 split out)
    k_gather_h<128><<<nb((long)M * 16, T), T>>>(aggH, bufH, csr, off, dinv, M);
    k_hgemm<128, false, true><<<gB, 256>>>(aggH, whh, bmu, blv, dinv,
                                           nullptr, out, out + (size_t)M * 64, M);
}

// round 16
// speedup vs baseline: 1.0916x; 1.0021x over previous
#include <cuda_runtime.h>
#include <cuda_fp16.h>
#include <cstdint>

// ---------------------------------------------------------------------------
// GCN-VAE encoder. Round 16: round-15 champion (gather/GEMM/scan FROZEN)
// + int4-vectorized k_hist / k_fill (4 edges per thread, scalar fallback).
// Gathers are at the L2-bandwidth floor (~1.02GB random reads @ ~8TB/s);
// remaining addressable time is CSR build + launch ramp.
// ---------------------------------------------------------------------------

#define N_NODES 100000
#define E_MAX   1700000

__device__ int    g_cnt   [N_NODES];
__device__ int    g_off   [N_NODES + 1];
__device__ int    g_cursor[N_NODES];
__device__ int    g_bsum  [128];
__device__ int    g_csr   [E_MAX];
__device__ float  g_dinv  [N_NODES];
__device__ __half g_xh  [(size_t)N_NODES * 64];      // fp16 dinv*x
__device__ __half g_aggH[(size_t)N_NODES * 128];     // fp16 aggregated features
__device__ __half g_bufH[(size_t)N_NODES * 128];     // fp16 dinv*hidden
__device__ __half g_wh1 [64  * 128];
__device__ __half g_wh2 [128 * 128];
__device__ __half g_whh [128 * 128];                 // [Wmu | Wlv]

// ----------------------------- setup / CSR ---------------------------------

__global__ void k_setup(int* __restrict__ cnt, int M,
                        const float* __restrict__ W1, const float* __restrict__ W2,
                        const float* __restrict__ Wmu, const float* __restrict__ Wlv,
                        __half* __restrict__ Wh1, __half* __restrict__ Wh2,
                        __half* __restrict__ Whh) {
    int i = blockIdx.x * blockDim.x + threadIdx.x;
    if (i < M) cnt[i] = 0;
    if (i < 64 * 128) Wh1[i] = __float2half_rn(W1[i]);
    if (i < 128 * 128) {
        Wh2[i] = __float2half_rn(W2[i]);
        int k = i >> 7, j = i & 127;
        Whh[i] = __float2half_rn(j < 64 ? Wmu[k * 64 + j] : Wlv[k * 64 + (j - 64)]);
    }
}

// 4 edges per thread, int4 index loads (caller guarantees E%4==0 + alignment)
__global__ void k_hist4(const int* __restrict__ dst, int* __restrict__ cnt, int E4) {
    int i = blockIdx.x * blockDim.x + threadIdx.x;
    if (i >= E4) return;
    int4 d = reinterpret_cast<const int4*>(dst)[i];
    atomicAdd(&cnt[d.x], 1);
    atomicAdd(&cnt[d.y], 1);
    atomicAdd(&cnt[d.z], 1);
    atomicAdd(&cnt[d.w], 1);
}

__global__ void k_hist(const int* __restrict__ dst, int* __restrict__ cnt, int E) {
    int i = blockIdx.x * blockDim.x + threadIdx.x;
    if (i < E) atomicAdd(&cnt[dst[i]], 1);
}

__global__ void k_scan1(const int* __restrict__ cnt, int* __restrict__ off,
                        int* __restrict__ bsum, int n) {
    __shared__ int s[256];
    const int tid = threadIdx.x;
    const int base = blockIdx.x * 1024 + tid * 4;
    int v[4], tsum = 0;
#pragma unroll
    for (int r = 0; r < 4; r++) {
        int idx = base + r;
        v[r] = (idx < n) ? cnt[idx] : 0;
        tsum += v[r];
    }
    s[tid] = tsum;
    __syncthreads();
    for (int d = 1; d < 256; d <<= 1) {
        int add = (tid >= d) ? s[tid - d] : 0;
        __syncthreads();
        s[tid] += add;
        __syncthreads();
    }
    int run = s[tid] - tsum;
#pragma unroll
    for (int r = 0; r < 4; r++) {
        int idx = base + r;
        if (idx < n) off[idx] = run;
        run += v[r];
    }
    if (tid == 255) bsum[blockIdx.x] = s[255];
}

// Fused: per-block bsum prefix + finalize off/cursor/dinv + x->fp16 prescale
__global__ void __launch_bounds__(256)
k_scan3_cvt(int* __restrict__ off, int* __restrict__ cursor,
            const int* __restrict__ bsum, const int* __restrict__ cnt,
            float* __restrict__ dinv, int n, int E, int nscan,
            const float* __restrict__ x, __half* __restrict__ xh) {
    __shared__ int s[128];
    __shared__ int pre;
    const int tid = threadIdx.x;
    const long base = (long)blockIdx.x * 256;

    if (base < n) {
        const int blk = (int)(base >> 10);
        if (tid < 128) s[tid] = (tid < blk && tid < nscan) ? bsum[tid] : 0;
        __syncthreads();
        if (tid < 64) s[tid] += s[tid + 64];
        __syncthreads();
        if (tid < 32) {
            int v = s[tid] + s[tid + 32];
#pragma unroll
            for (int o = 16; o > 0; o >>= 1)
                v += __shfl_down_sync(0xffffffffu, v, o);
            if (tid == 0) pre = v;
        }
        __syncthreads();

        int i = (int)base + tid;
        if (i < n) {
            int o = off[i] + pre;
            off[i] = o;
            cursor[i] = o;
            dinv[i] = rsqrtf((float)(cnt[i] + 1));
        }
        if (i == 0) off[n] = E;
    }

    long j = base + tid;
    if (j < (long)n * 8) {
        int row = (int)(j >> 3);
        float w = rsqrtf((float)(cnt[row] + 1));
        float4 a = reinterpret_cast<const float4*>(x)[2 * j];
        float4 b = reinterpret_cast<const float4*>(x)[2 * j + 1];
        __half2 h[4];
        h[0] = __float22half2_rn(make_float2(w * a.x, w * a.y));
        h[1] = __float22half2_rn(make_float2(w * a.z, w * a.w));
        h[2] = __float22half2_rn(make_float2(w * b.x, w * b.y));
        h[3] = __float22half2_rn(make_float2(w * b.z, w * b.w));
        reinterpret_cast<uint4*>(xh)[j] = *reinterpret_cast<uint4*>(h);
    }
}

// 4 edges per thread, int4 loads of src+dst
__global__ void k_fill4(const int* __restrict__ src, const int* __restrict__ dst,
                        int* __restrict__ cursor, int* __restrict__ csr, int E4) {
    int i = blockIdx.x * blockDim.x + threadIdx.x;
    if (i >= E4) return;
    int4 sv = reinterpret_cast<const int4*>(src)[i];
    int4 dv = reinterpret_cast<const int4*>(dst)[i];
    csr[atomicAdd(&cursor[dv.x], 1)] = sv.x;
    csr[atomicAdd(&cursor[dv.y], 1)] = sv.y;
    csr[atomicAdd(&cursor[dv.z], 1)] = sv.z;
    csr[atomicAdd(&cursor[dv.w], 1)] = sv.w;
}

__global__ void k_fill(const int* __restrict__ src, const int* __restrict__ dst,
                       int* __restrict__ cursor, int* __restrict__ csr, int E) {
    int i = blockIdx.x * blockDim.x + threadIdx.x;
    if (i < E) {
        int pos = atomicAdd(&cursor[dst[i]], 1);
        csr[pos] = src[i];
    }
}

// ----------------------------- gather SpMM (FROZEN) -------------------------

template <int D>
__global__ void __launch_bounds__(256)
k_gather_h(__half* __restrict__ acc, const __half* __restrict__ t,
           const int* __restrict__ csr, const int* __restrict__ off,
           const float* __restrict__ dinv, int n) {
    constexpr int G = D / 8;
    int gid  = (blockIdx.x * blockDim.x + threadIdx.x) / G;
    int lane = threadIdx.x % G;
    if (gid >= n) return;

    float a[8];
    {
        uint4 u = *reinterpret_cast<const uint4*>(t + (size_t)gid * D + lane * 8);
        const __half2* h = reinterpret_cast<const __half2*>(&u);
#pragma unroll
        for (int p = 0; p < 4; p++) {
            float2 f = __half22float2(h[p]);
            a[2 * p]     = f.x;
            a[2 * p + 1] = f.y;
        }
    }

    int e   = off[gid];
    int end = off[gid + 1];
    for (; e + 4 <= end; e += 4) {
        int s0 = csr[e], s1 = csr[e + 1], s2 = csr[e + 2], s3 = csr[e + 3];
        uint4 u0 = *reinterpret_cast<const uint4*>(t + (size_t)s0 * D + lane * 8);
        uint4 u1 = *reinterpret_cast<const uint4*>(t + (size_t)s1 * D + lane * 8);
        uint4 u2 = *reinterpret_cast<const uint4*>(t + (size_t)s2 * D + lane * 8);
        uint4 u3 = *reinterpret_cast<const uint4*>(t + (size_t)s3 * D + lane * 8);
        const __half2* h0 = reinterpret_cast<const __half2*>(&u0);
        const __half2* h1 = reinterpret_cast<const __half2*>(&u1);
        const __half2* h2 = reinterpret_cast<const __half2*>(&u2);
        const __half2* h3 = reinterpret_cast<const __half2*>(&u3);
#pragma unroll
        for (int p = 0; p < 4; p++) {
            __half2 s01 = __hadd2(h0[p], h1[p]);   // fp16 pairwise pre-add
            __half2 s23 = __hadd2(h2[p], h3[p]);
            float2 f01 = __half22float2(s01);
            float2 f23 = __half22float2(s23);
            a[2 * p]     += f01.x + f23.x;
            a[2 * p + 1] += f01.y + f23.y;
        }
    }
    if (e + 2 <= end) {
        int s0 = csr[e], s1 = csr[e + 1];
        e += 2;
        uint4 u0 = *reinterpret_cast<const uint4*>(t + (size_t)s0 * D + lane * 8);
        uint4 u1 = *reinterpret_cast<const uint4*>(t + (size_t)s1 * D + lane * 8);
        const __half2* h0 = reinterpret_cast<const __half2*>(&u0);
        const __half2* h1 = reinterpret_cast<const __half2*>(&u1);
#pragma unroll
        for (int p = 0; p < 4; p++) {
            __half2 s01 = __hadd2(h0[p], h1[p]);
            float2 f01 = __half22float2(s01);
            a[2 * p]     += f01.x;
            a[2 * p + 1] += f01.y;
        }
    }
    if (e < end) {
        int s0 = csr[e];
        uint4 u0 = *reinterpret_cast<const uint4*>(t + (size_t)s0 * D + lane * 8);
        const __half2* h0 = reinterpret_cast<const __half2*>(&u0);
#pragma unroll
        for (int p = 0; p < 4; p++) {
            float2 f0 = __half22float2(h0[p]);
            a[2 * p]     += f0.x;
            a[2 * p + 1] += f0.y;
        }
    }

    float w = dinv[gid];
    __half2 hv[4];
#pragma unroll
    for (int p = 0; p < 4; p++)
        hv[p] = __float22half2_rn(make_float2(w * a[2 * p], w * a[2 * p + 1]));
    *reinterpret_cast<uint4*>(acc + (size_t)gid * D + lane * 8) =
        *reinterpret_cast<uint4*>(hv);
}

// ------------------------------- HMMA GEMM (FROZEN) -------------------------

template <int K, bool RELU, bool SPLIT>
__global__ void __launch_bounds__(256)
k_hgemm(const __half* __restrict__ A, const __half* __restrict__ Wh,
        const float* __restrict__ b0, const float* __restrict__ b1,
        const float* __restrict__ dinv,
        __half* __restrict__ H, float* __restrict__ C0, float* __restrict__ C1,
        int M) {
    __shared__ __half Xs[128][72];
    __shared__ __half Ws[64][136];

    const int tid = threadIdx.x;
    const int wid = tid >> 5;
    const int lane = tid & 31;
    const int mg = wid >> 1;
    const int ng = wid & 1;
    const int row0 = blockIdx.x * 128;

    float acc[2][8][4];
#pragma unroll
    for (int mt = 0; mt < 2; mt++)
#pragma unroll
        for (int nt = 0; nt < 8; nt++)
#pragma unroll
            for (int q = 0; q < 4; q++) acc[mt][nt][q] = 0.f;

    for (int kc = 0; kc < K; kc += 64) {
#pragma unroll
        for (int i = tid; i < 128 * 8; i += 256) {
            int r = i >> 3, c8 = i & 7;
            int grow = row0 + r;
            uint4 v = make_uint4(0u, 0u, 0u, 0u);
            if (grow < M)
                v = *reinterpret_cast<const uint4*>(A + (size_t)grow * K + kc + c8 * 8);
            *reinterpret_cast<uint4*>(&Xs[r][c8 * 8]) = v;
        }
#pragma unroll
        for (int i = tid; i < 64 * 16; i += 256) {
            int k = i >> 4, n8 = i & 15;
            uint4 v = *reinterpret_cast<const uint4*>(Wh + (size_t)(kc + k) * 128 + n8 * 8);
            *reinterpret_cast<uint4*>(&Ws[k][n8 * 8]) = v;
        }
        __syncthreads();

#pragma unroll
        for (int ks = 0; ks < 4; ks++) {
            uint32_t af[2][4];
#pragma unroll
            for (int mt = 0; mt < 2; mt++) {
                int r = mg * 32 + mt * 16 + (lane & 15);
                int c = ks * 16 + (lane >> 4) * 8;
                uint32_t addr = (uint32_t)__cvta_generic_to_shared(&Xs[r][c]);
                asm volatile(
                    "ldmatrix.sync.aligned.m8n8.x4.shared.b16 {%0,%1,%2,%3}, [%4];"
                    : "=r"(af[mt][0]), "=r"(af[mt][1]), "=r"(af[mt][2]), "=r"(af[mt][3])
                    : "r"(addr));
            }
#pragma unroll
            for (int nt = 0; nt < 8; nt++) {
                int k = ks * 16 + (lane & 15);
                int c = ng * 64 + nt * 8;
                uint32_t addr = (uint32_t)__cvta_generic_to_shared(&Ws[k][c]);
                uint32_t bf0, bf1;
                asm volatile(
                    "ldmatrix.sync.aligned.m8n8.x2.trans.shared.b16 {%0,%1}, [%2];"
                    : "=r"(bf0), "=r"(bf1) : "r"(addr));
#pragma unroll
                for (int mt = 0; mt < 2; mt++) {
                    asm volatile(
                        "mma.sync.aligned.m16n8k16.row.col.f32.f16.f16.f32 "
                        "{%0,%1,%2,%3}, {%4,%5,%6,%7}, {%8,%9}, {%0,%1,%2,%3};"
                        : "+f"(acc[mt][nt][0]), "+f"(acc[mt][nt][1]),
                          "+f"(acc[mt][nt][2]), "+f"(acc[mt][nt][3])
                        : "r"(af[mt][0]), "r"(af[mt][1]), "r"(af[mt][2]), "r"(af[mt][3]),
                          "r"(bf0), "r"(bf1));
                }
            }
        }
        __syncthreads();
    }

    const int tig = lane & 3;
    const int grp = lane >> 2;
#pragma unroll
    for (int mt = 0; mt < 2; mt++) {
#pragma unroll
        for (int nt = 0; nt < 8; nt++) {
            int c = ng * 64 + nt * 8 + tig * 2;
#pragma unroll
            for (int hf = 0; hf < 2; hf++) {
                int r = row0 + mg * 32 + mt * 16 + grp + hf * 8;
                if (r >= M) continue;
                float v0 = acc[mt][nt][hf * 2 + 0];
                float v1 = acc[mt][nt][hf * 2 + 1];
                if (!SPLIT) {
                    v0 += b0[c]; v1 += b0[c + 1];
                    if (RELU) { v0 = fmaxf(v0, 0.f); v1 = fmaxf(v1, 0.f); }
                    float dv = dinv[r];
                    *reinterpret_cast<__half2*>(H + (size_t)r * 128 + c) =
                        __floats2half2_rn(v0 * dv, v1 * dv);
                } else if (c < 64) {
                    v0 += b0[c]; v1 += b0[c + 1];
                    *reinterpret_cast<float2*>(C0 + (size_t)r * 64 + c) =
                        make_float2(v0, v1);
                } else {
                    v0 += b1[c - 64]; v1 += b1[c - 63];
                    *reinterpret_cast<float2*>(C1 + (size_t)r * 64 + (c - 64)) =
                        make_float2(v0, v1);
                }
            }
        }
    }
}

// ------------------------------- launcher ----------------------------------

extern "C" void kernel_launch(void* const* d_in, const int* in_sizes, int n_in,
                              void* d_out, int out_size) {
    const float* x   = (const float*)d_in[0];
    const int*   ei  = (const int*)  d_in[1];
    const float* W1  = (const float*)d_in[2];
    const float* b1  = (const float*)d_in[3];
    const float* W2  = (const float*)d_in[4];
    const float* b2  = (const float*)d_in[5];
    const float* Wmu = (const float*)d_in[6];
    const float* bmu = (const float*)d_in[7];
    const float* Wlv = (const float*)d_in[8];
    const float* blv = (const float*)d_in[9];
    float* out = (float*)d_out;

    const int M = in_sizes[0] / 64;
    const int E = in_sizes[1] / 2;
    const int* src = ei;
    const int* dst = ei + E;

    int *cnt, *off, *cursor, *bsum, *csr;
    float *dinv;
    __half *xh, *aggH, *bufH, *wh1, *wh2, *whh;
    cudaGetSymbolAddress((void**)&cnt,    g_cnt);
    cudaGetSymbolAddress((void**)&off,    g_off);
    cudaGetSymbolAddress((void**)&cursor, g_cursor);
    cudaGetSymbolAddress((void**)&bsum,   g_bsum);
    cudaGetSymbolAddress((void**)&csr,    g_csr);
    cudaGetSymbolAddress((void**)&dinv,   g_dinv);
    cudaGetSymbolAddress((void**)&xh,     g_xh);
    cudaGetSymbolAddress((void**)&aggH,   g_aggH);
    cudaGetSymbolAddress((void**)&bufH,   g_bufH);
    cudaGetSymbolAddress((void**)&wh1,    g_wh1);
    cudaGetSymbolAddress((void**)&wh2,    g_wh2);
    cudaGetSymbolAddress((void**)&whh,    g_whh);

    const int T = 256;
    auto nb = [](long n, int t) { return (int)((n + t - 1) / t); };
    const int nscan = nb(M, 1024);
    const int gB = nb(M, 128);

    // vector path usable when E%4==0 and both index halves are 16B-aligned
    const bool vec4 = ((E & 3) == 0) &&
                      ((reinterpret_cast<uintptr_t>(src) & 15u) == 0) &&
                      ((reinterpret_cast<uintptr_t>(dst) & 15u) == 0);

    // setup + CSR build (by dst) + fused scan-finalize/dinv/x-prescale
    k_setup<<<nb(M, T), T>>>(cnt, M, W1, W2, Wmu, Wlv, wh1, wh2, whh);
    if (vec4) k_hist4<<<nb(E / 4, T), T>>>(dst, cnt, E / 4);
    else      k_hist <<<nb(E, T), T>>>(dst, cnt, E);
    k_scan1<<<nscan, 256>>>(cnt, off, bsum, M);
    k_scan3_cvt<<<nb((long)M * 8, T), T>>>(off, cursor, bsum, cnt, dinv,
                                           M, E, nscan, x, xh);
    if (vec4) k_fill4<<<nb(E / 4, T), T>>>(src, dst, cursor, csr, E / 4);
    else      k_fill <<<nb(E, T), T>>>(src, dst, cursor, csr, E);

    // layer 1: gather xh (64) -> HMMA 64->128 relu -> h1' fp16 (prescaled)
    k_gather_h<64><<<nb((long)M * 8, T), T>>>(aggH, xh, csr, off, dinv, M);
    k_hgemm<64, true, false><<<gB, 256>>>(aggH, wh1, b1, nullptr, dinv,
                                          bufH, nullptr, nullptr, M);

    // layer 2: gather h1' (128) -> HMMA 128->128 relu -> h2' fp16 (prescaled)
    k_gather_h<128><<<nb((long)M * 16, T), T>>>(aggH, bufH, csr, off, dinv, M);
    k_hgemm<128, true, false><<<gB, 256>>>(aggH, wh2, b2, nullptr, dinv,
                                           bufH, nullptr, nullptr, M);

    // heads: gather h2' (128) once -> fused mu|logvar HMMA (fp32 split out)
    k_gather_h<128><<<nb((long)M * 16, T), T>>>(aggH, bufH, csr, off, dinv, M);
    k_hgemm<128, false, true><<<gB, 256>>>(aggH, whh, bmu, blv, dinv,
                                           nullptr, out, out + (size_t)M * 64, M);
}

// round 17
// speedup vs baseline: 1.1136x; 1.0201x over previous
#include <cuda_runtime.h>
#include <cuda_fp16.h>
#include <cstdint>

// ---------------------------------------------------------------------------
// GCN-VAE encoder. Round 17: round-16 champion (all kernel bodies FROZEN)
// + Programmatic Dependent Launch across the serial chain:
//   each kernel triggers dependents at block start (pre-positions the next
//   grid during this kernel's tail wave) and waits on its predecessor before
//   touching data. Removes launch-gap + ramp from the critical path.
// ---------------------------------------------------------------------------

#define N_NODES 100000
#define E_MAX   1700000

// PDL prologue: allow dependents to launch, then wait for predecessor data.
#define PDL() do {                                              \
    asm volatile("griddepcontrol.launch_dependents;");          \
    asm volatile("griddepcontrol.wait;" ::: "memory");          \
} while (0)

__device__ int    g_cnt   [N_NODES];
__device__ int    g_off   [N_NODES + 1];
__device__ int    g_cursor[N_NODES];
__device__ int    g_bsum  [128];
__device__ int    g_csr   [E_MAX];
__device__ float  g_dinv  [N_NODES];
__device__ __half g_xh  [(size_t)N_NODES * 64];      // fp16 dinv*x
__device__ __half g_aggH[(size_t)N_NODES * 128];     // fp16 aggregated features
__device__ __half g_bufH[(size_t)N_NODES * 128];     // fp16 dinv*hidden
__device__ __half g_wh1 [64  * 128];
__device__ __half g_wh2 [128 * 128];
__device__ __half g_whh [128 * 128];                 // [Wmu | Wlv]

// ----------------------------- setup / CSR ---------------------------------

__global__ void k_setup(int* __restrict__ cnt, int M,
                        const float* __restrict__ W1, const float* __restrict__ W2,
                        const float* __restrict__ Wmu, const float* __restrict__ Wlv,
                        __half* __restrict__ Wh1, __half* __restrict__ Wh2,
                        __half* __restrict__ Whh) {
    asm volatile("griddepcontrol.launch_dependents;");
    int i = blockIdx.x * blockDim.x + threadIdx.x;
    if (i < M) cnt[i] = 0;
    if (i < 64 * 128) Wh1[i] = __float2half_rn(W1[i]);
    if (i < 128 * 128) {
        Wh2[i] = __float2half_rn(W2[i]);
        int k = i >> 7, j = i & 127;
        Whh[i] = __float2half_rn(j < 64 ? Wmu[k * 64 + j] : Wlv[k * 64 + (j - 64)]);
    }
}

__global__ void k_hist4(const int* __restrict__ dst, int* __restrict__ cnt, int E4) {
    PDL();
    int i = blockIdx.x * blockDim.x + threadIdx.x;
    if (i >= E4) return;
    int4 d = reinterpret_cast<const int4*>(dst)[i];
    atomicAdd(&cnt[d.x], 1);
    atomicAdd(&cnt[d.y], 1);
    atomicAdd(&cnt[d.z], 1);
    atomicAdd(&cnt[d.w], 1);
}

__global__ void k_hist(const int* __restrict__ dst, int* __restrict__ cnt, int E) {
    PDL();
    int i = blockIdx.x * blockDim.x + threadIdx.x;
    if (i < E) atomicAdd(&cnt[dst[i]], 1);
}

__global__ void k_scan1(const int* __restrict__ cnt, int* __restrict__ off,
                        int* __restrict__ bsum, int n) {
    PDL();
    __shared__ int s[256];
    const int tid = threadIdx.x;
    const int base = blockIdx.x * 1024 + tid * 4;
    int v[4], tsum = 0;
#pragma unroll
    for (int r = 0; r < 4; r++) {
        int idx = base + r;
        v[r] = (idx < n) ? cnt[idx] : 0;
        tsum += v[r];
    }
    s[tid] = tsum;
    __syncthreads();
    for (int d = 1; d < 256; d <<= 1) {
        int add = (tid >= d) ? s[tid - d] : 0;
        __syncthreads();
        s[tid] += add;
        __syncthreads();
    }
    int run = s[tid] - tsum;
#pragma unroll
    for (int r = 0; r < 4; r++) {
        int idx = base + r;
        if (idx < n) off[idx] = run;
        run += v[r];
    }
    if (tid == 255) bsum[blockIdx.x] = s[255];
}

// Fused: per-block bsum prefix + finalize off/cursor/dinv + x->fp16 prescale
__global__ void __launch_bounds__(256)
k_scan3_cvt(int* __restrict__ off, int* __restrict__ cursor,
            const int* __restrict__ bsum, const int* __restrict__ cnt,
            float* __restrict__ dinv, int n, int E, int nscan,
            const float* __restrict__ x, __half* __restrict__ xh) {
    PDL();
    __shared__ int s[128];
    __shared__ int pre;
    const int tid = threadIdx.x;
    const long base = (long)blockIdx.x * 256;

    if (base < n) {
        const int blk = (int)(base >> 10);
        if (tid < 128) s[tid] = (tid < blk && tid < nscan) ? bsum[tid] : 0;
        __syncthreads();
        if (tid < 64) s[tid] += s[tid + 64];
        __syncthreads();
        if (tid < 32) {
            int v = s[tid] + s[tid + 32];
#pragma unroll
            for (int o = 16; o > 0; o >>= 1)
                v += __shfl_down_sync(0xffffffffu, v, o);
            if (tid == 0) pre = v;
        }
        __syncthreads();

        int i = (int)base + tid;
        if (i < n) {
            int o = off[i] + pre;
            off[i] = o;
            cursor[i] = o;
            dinv[i] = rsqrtf((float)(cnt[i] + 1));
        }
        if (i == 0) off[n] = E;
    }

    long j = base + tid;
    if (j < (long)n * 8) {
        int row = (int)(j >> 3);
        float w = rsqrtf((float)(cnt[row] + 1));
        float4 a = reinterpret_cast<const float4*>(x)[2 * j];
        float4 b = reinterpret_cast<const float4*>(x)[2 * j + 1];
        __half2 h[4];
        h[0] = __float22half2_rn(make_float2(w * a.x, w * a.y));
        h[1] = __float22half2_rn(make_float2(w * a.z, w * a.w));
        h[2] = __float22half2_rn(make_float2(w * b.x, w * b.y));
        h[3] = __float22half2_rn(make_float2(w * b.z, w * b.w));
        reinterpret_cast<uint4*>(xh)[j] = *reinterpret_cast<uint4*>(h);
    }
}

__global__ void k_fill4(const int* __restrict__ src, const int* __restrict__ dst,
                        int* __restrict__ cursor, int* __restrict__ csr, int E4) {
    PDL();
    int i = blockIdx.x * blockDim.x + threadIdx.x;
    if (i >= E4) return;
    int4 sv = reinterpret_cast<const int4*>(src)[i];
    int4 dv = reinterpret_cast<const int4*>(dst)[i];
    csr[atomicAdd(&cursor[dv.x], 1)] = sv.x;
    csr[atomicAdd(&cursor[dv.y], 1)] = sv.y;
    csr[atomicAdd(&cursor[dv.z], 1)] = sv.z;
    csr[atomicAdd(&cursor[dv.w], 1)] = sv.w;
}

__global__ void k_fill(const int* __restrict__ src, const int* __restrict__ dst,
                       int* __restrict__ cursor, int* __restrict__ csr, int E) {
    PDL();
    int i = blockIdx.x * blockDim.x + threadIdx.x;
    if (i < E) {
        int pos = atomicAdd(&cursor[dst[i]], 1);
        csr[pos] = src[i];
    }
}

// ----------------------------- gather SpMM (FROZEN body) --------------------

template <int D>
__global__ void __launch_bounds__(256)
k_gather_h(__half* __restrict__ acc, const __half* __restrict__ t,
           const int* __restrict__ csr, const int* __restrict__ off,
           const float* __restrict__ dinv, int n) {
    PDL();
    constexpr int G = D / 8;
    int gid  = (blockIdx.x * blockDim.x + threadIdx.x) / G;
    int lane = threadIdx.x % G;
    if (gid >= n) return;

    float a[8];
    {
        uint4 u = *reinterpret_cast<const uint4*>(t + (size_t)gid * D + lane * 8);
        const __half2* h = reinterpret_cast<const __half2*>(&u);
#pragma unroll
        for (int p = 0; p < 4; p++) {
            float2 f = __half22float2(h[p]);
            a[2 * p]     = f.x;
            a[2 * p + 1] = f.y;
        }
    }

    int e   = off[gid];
    int end = off[gid + 1];
    for (; e + 4 <= end; e += 4) {
        int s0 = csr[e], s1 = csr[e + 1], s2 = csr[e + 2], s3 = csr[e + 3];
        uint4 u0 = *reinterpret_cast<const uint4*>(t + (size_t)s0 * D + lane * 8);
        uint4 u1 = *reinterpret_cast<const uint4*>(t + (size_t)s1 * D + lane * 8);
        uint4 u2 = *reinterpret_cast<const uint4*>(t + (size_t)s2 * D + lane * 8);
        uint4 u3 = *reinterpret_cast<const uint4*>(t + (size_t)s3 * D + lane * 8);
        const __half2* h0 = reinterpret_cast<const __half2*>(&u0);
        const __half2* h1 = reinterpret_cast<const __half2*>(&u1);
        const __half2* h2 = reinterpret_cast<const __half2*>(&u2);
        const __half2* h3 = reinterpret_cast<const __half2*>(&u3);
#pragma unroll
        for (int p = 0; p < 4; p++) {
            __half2 s01 = __hadd2(h0[p], h1[p]);   // fp16 pairwise pre-add
            __half2 s23 = __hadd2(h2[p], h3[p]);
            float2 f01 = __half22float2(s01);
            float2 f23 = __half22float2(s23);
            a[2 * p]     += f01.x + f23.x;
            a[2 * p + 1] += f01.y + f23.y;
        }
    }
    if (e + 2 <= end) {
        int s0 = csr[e], s1 = csr[e + 1];
        e += 2;
        uint4 u0 = *reinterpret_cast<const uint4*>(t + (size_t)s0 * D + lane * 8);
        uint4 u1 = *reinterpret_cast<const uint4*>(t + (size_t)s1 * D + lane * 8);
        const __half2* h0 = reinterpret_cast<const __half2*>(&u0);
        const __half2* h1 = reinterpret_cast<const __half2*>(&u1);
#pragma unroll
        for (int p = 0; p < 4; p++) {
            __half2 s01 = __hadd2(h0[p], h1[p]);
            float2 f01 = __half22float2(s01);
            a[2 * p]     += f01.x;
            a[2 * p + 1] += f01.y;
        }
    }
    if (e < end) {
        int s0 = csr[e];
        uint4 u0 = *reinterpret_cast<const uint4*>(t + (size_t)s0 * D + lane * 8);
        const __half2* h0 = reinterpret_cast<const __half2*>(&u0);
#pragma unroll
        for (int p = 0; p < 4; p++) {
            float2 f0 = __half22float2(h0[p]);
            a[2 * p]     += f0.x;
            a[2 * p + 1] += f0.y;
        }
    }

    float w = dinv[gid];
    __half2 hv[4];
#pragma unroll
    for (int p = 0; p < 4; p++)
        hv[p] = __float22half2_rn(make_float2(w * a[2 * p], w * a[2 * p + 1]));
    *reinterpret_cast<uint4*>(acc + (size_t)gid * D + lane * 8) =
        *reinterpret_cast<uint4*>(hv);
}

// ------------------------------- HMMA GEMM (FROZEN body) --------------------

template <int K, bool RELU, bool SPLIT>
__global__ void __launch_bounds__(256)
k_hgemm(const __half* __restrict__ A, const __half* __restrict__ Wh,
        const float* __restrict__ b0, const float* __restrict__ b1,
        const float* __restrict__ dinv,
        __half* __restrict__ H, float* __restrict__ C0, float* __restrict__ C1,
        int M) {
    PDL();
    __shared__ __half Xs[128][72];
    __shared__ __half Ws[64][136];

    const int tid = threadIdx.x;
    const int wid = tid >> 5;
    const int lane = tid & 31;
    const int mg = wid >> 1;
    const int ng = wid & 1;
    const int row0 = blockIdx.x * 128;

    float acc[2][8][4];
#pragma unroll
    for (int mt = 0; mt < 2; mt++)
#pragma unroll
        for (int nt = 0; nt < 8; nt++)
#pragma unroll
            for (int q = 0; q < 4; q++) acc[mt][nt][q] = 0.f;

    for (int kc = 0; kc < K; kc += 64) {
#pragma unroll
        for (int i = tid; i < 128 * 8; i += 256) {
            int r = i >> 3, c8 = i & 7;
            int grow = row0 + r;
            uint4 v = make_uint4(0u, 0u, 0u, 0u);
            if (grow < M)
                v = *reinterpret_cast<const uint4*>(A + (size_t)grow * K + kc + c8 * 8);
            *reinterpret_cast<uint4*>(&Xs[r][c8 * 8]) = v;
        }
#pragma unroll
        for (int i = tid; i < 64 * 16; i += 256) {
            int k = i >> 4, n8 = i & 15;
            uint4 v = *reinterpret_cast<const uint4*>(Wh + (size_t)(kc + k) * 128 + n8 * 8);
            *reinterpret_cast<uint4*>(&Ws[k][n8 * 8]) = v;
        }
        __syncthreads();

#pragma unroll
        for (int ks = 0; ks < 4; ks++) {
            uint32_t af[2][4];
#pragma unroll
            for (int mt = 0; mt < 2; mt++) {
                int r = mg * 32 + mt * 16 + (lane & 15);
                int c = ks * 16 + (lane >> 4) * 8;
                uint32_t addr = (uint32_t)__cvta_generic_to_shared(&Xs[r][c]);
                asm volatile(
                    "ldmatrix.sync.aligned.m8n8.x4.shared.b16 {%0,%1,%2,%3}, [%4];"
                    : "=r"(af[mt][0]), "=r"(af[mt][1]), "=r"(af[mt][2]), "=r"(af[mt][3])
                    : "r"(addr));
            }
#pragma unroll
            for (int nt = 0; nt < 8; nt++) {
                int k = ks * 16 + (lane & 15);
                int c = ng * 64 + nt * 8;
                uint32_t addr = (uint32_t)__cvta_generic_to_shared(&Ws[k][c]);
                uint32_t bf0, bf1;
                asm volatile(
                    "ldmatrix.sync.aligned.m8n8.x2.trans.shared.b16 {%0,%1}, [%2];"
                    : "=r"(bf0), "=r"(bf1) : "r"(addr));
#pragma unroll
                for (int mt = 0; mt < 2; mt++) {
                    asm volatile(
                        "mma.sync.aligned.m16n8k16.row.col.f32.f16.f16.f32 "
                        "{%0,%1,%2,%3}, {%4,%5,%6,%7}, {%8,%9}, {%0,%1,%2,%3};"
                        : "+f"(acc[mt][nt][0]), "+f"(acc[mt][nt][1]),
                          "+f"(acc[mt][nt][2]), "+f"(acc[mt][nt][3])
                        : "r"(af[mt][0]), "r"(af[mt][1]), "r"(af[mt][2]), "r"(af[mt][3]),
                          "r"(bf0), "r"(bf1));
                }
            }
        }
        __syncthreads();
    }

    const int tig = lane & 3;
    const int grp = lane >> 2;
#pragma unroll
    for (int mt = 0; mt < 2; mt++) {
#pragma unroll
        for (int nt = 0; nt < 8; nt++) {
            int c = ng * 64 + nt * 8 + tig * 2;
#pragma unroll
            for (int hf = 0; hf < 2; hf++) {
                int r = row0 + mg * 32 + mt * 16 + grp + hf * 8;
                if (r >= M) continue;
                float v0 = acc[mt][nt][hf * 2 + 0];
                float v1 = acc[mt][nt][hf * 2 + 1];
                if (!SPLIT) {
                    v0 += b0[c]; v1 += b0[c + 1];
                    if (RELU) { v0 = fmaxf(v0, 0.f); v1 = fmaxf(v1, 0.f); }
                    float dv = dinv[r];
                    *reinterpret_cast<__half2*>(H + (size_t)r * 128 + c) =
                        __floats2half2_rn(v0 * dv, v1 * dv);
                } else if (c < 64) {
                    v0 += b0[c]; v1 += b0[c + 1];
                    *reinterpret_cast<float2*>(C0 + (size_t)r * 64 + c) =
                        make_float2(v0, v1);
                } else {
                    v0 += b1[c - 64]; v1 += b1[c - 63];
                    *reinterpret_cast<float2*>(C1 + (size_t)r * 64 + (c - 64)) =
                        make_float2(v0, v1);
                }
            }
        }
    }
}

// ------------------------------- launcher ----------------------------------

template <typename Kern, typename... Args>
static inline void launch_pdl(int grid, int block, Kern k, Args... args) {
    cudaLaunchConfig_t cfg = {};
    cfg.gridDim  = dim3((unsigned)grid, 1, 1);
    cfg.blockDim = dim3((unsigned)block, 1, 1);
    cudaLaunchAttribute attr[1];
    attr[0].id = cudaLaunchAttributeProgrammaticStreamSerialization;
    attr[0].val.programmaticStreamSerializationAllowed = 1;
    cfg.attrs = attr;
    cfg.numAttrs = 1;
    cudaLaunchKernelEx(&cfg, k, args...);
}

extern "C" void kernel_launch(void* const* d_in, const int* in_sizes, int n_in,
                              void* d_out, int out_size) {
    const float* x   = (const float*)d_in[0];
    const int*   ei  = (const int*)  d_in[1];
    const float* W1  = (const float*)d_in[2];
    const float* b1  = (const float*)d_in[3];
    const float* W2  = (const float*)d_in[4];
    const float* b2  = (const float*)d_in[5];
    const float* Wmu = (const float*)d_in[6];
    const float* bmu = (const float*)d_in[7];
    const float* Wlv = (const float*)d_in[8];
    const float* blv = (const float*)d_in[9];
    float* out = (float*)d_out;

    const int M = in_sizes[0] / 64;
    const int E = in_sizes[1] / 2;
    const int* src = ei;
    const int* dst = ei + E;

    int *cnt, *off, *cursor, *bsum, *csr;
    float *dinv;
    __half *xh, *aggH, *bufH, *wh1, *wh2, *whh;
    cudaGetSymbolAddress((void**)&cnt,    g_cnt);
    cudaGetSymbolAddress((void**)&off,    g_off);
    cudaGetSymbolAddress((void**)&cursor, g_cursor);
    cudaGetSymbolAddress((void**)&bsum,   g_bsum);
    cudaGetSymbolAddress((void**)&csr,    g_csr);
    cudaGetSymbolAddress((void**)&dinv,   g_dinv);
    cudaGetSymbolAddress((void**)&xh,     g_xh);
    cudaGetSymbolAddress((void**)&aggH,   g_aggH);
    cudaGetSymbolAddress((void**)&bufH,   g_bufH);
    cudaGetSymbolAddress((void**)&wh1,    g_wh1);
    cudaGetSymbolAddress((void**)&wh2,    g_wh2);
    cudaGetSymbolAddress((void**)&whh,    g_whh);

    const int T = 256;
    auto nb = [](long n, int t) { return (int)((n + t - 1) / t); };
    const int nscan = nb(M, 1024);
    const int gB = nb(M, 128);

    const bool vec4 = ((E & 3) == 0) &&
                      ((reinterpret_cast<uintptr_t>(src) & 15u) == 0) &&
                      ((reinterpret_cast<uintptr_t>(dst) & 15u) == 0);

    // setup + CSR build (by dst) + fused scan-finalize/dinv/x-prescale.
    // Entire chain uses programmatic dependent launch.
    launch_pdl(nb(M, T), T, k_setup, cnt, M, W1, W2, Wmu, Wlv, wh1, wh2, whh);
    if (vec4) launch_pdl(nb(E / 4, T), T, k_hist4, dst, cnt, E / 4);
    else      launch_pdl(nb(E, T), T, k_hist, dst, cnt, E);
    launch_pdl(nscan, 256, k_scan1, cnt, off, bsum, M);
    launch_pdl(nb((long)M * 8, T), T, k_scan3_cvt,
               off, cursor, bsum, (const int*)cnt, dinv, M, E, nscan, x, xh);
    if (vec4) launch_pdl(nb(E / 4, T), T, k_fill4, src, dst, cursor, csr, E / 4);
    else      launch_pdl(nb(E, T), T, k_fill, src, dst, cursor, csr, E);

    // layer 1: gather xh (64) -> HMMA 64->128 relu -> h1' fp16 (prescaled)
    launch_pdl(nb((long)M * 8, T), T, k_gather_h<64>,
               aggH, (const __half*)xh, (const int*)csr, (const int*)off,
               (const float*)dinv, M);
    launch_pdl(gB, 256, k_hgemm<64, true, false>,
               (const __half*)aggH, (const __half*)wh1, b1, (const float*)nullptr,
               (const float*)dinv, bufH, (float*)nullptr, (float*)nullptr, M);

    // layer 2: gather h1' (128) -> HMMA 128->128 relu -> h2' fp16 (prescaled)
    launch_pdl(nb((long)M * 16, T), T, k_gather_h<128>,
               aggH, (const __half*)bufH, (const int*)csr, (const int*)off,
               (const float*)dinv, M);
    launch_pdl(gB, 256, k_hgemm<128, true, false>,
               (const __half*)aggH, (const __half*)wh2, b2, (const float*)nullptr,
               (const float*)dinv, bufH, (float*)nullptr, (float*)nullptr, M);

    // heads: gather h2' (128) once -> fused mu|logvar HMMA (fp32 split out)
    launch_pdl(nb((long)M * 16, T), T, k_gather_h<128>,
               aggH, (const __half*)bufH, (const int*)csr, (const int*)off,
               (const float*)dinv, M);
    launch_pdl(gB, 256, k_hgemm<128, false, true>,
               (const __half*)aggH, (const __half*)whh, bmu, blv,
               (const float*)dinv, (__half*)nullptr, out, out + (size_t)M * 64, M);
}